// round 2
// baseline (speedup 1.0000x reference)
#include <cuda_runtime.h>

#define D_MODEL   1024
#define NUM_HEADS 16
#define HEAD_DIM  64
#define BATCH     4
#define SEQ       2048
#define MTOT      (BATCH * SEQ)

// Scratch (allocation-free: __device__ globals). 4 x 32 MB.
__device__ float g_Q [MTOT * D_MODEL];
__device__ float g_K [MTOT * D_MODEL];
__device__ float g_V [MTOT * D_MODEL];
__device__ float g_AO[MTOT * D_MODEL];

// ---------------------------------------------------------------------------
// GEMM (NT): C[M,N] = A[M,K] @ W[N,K]^T + bias[N]
// A row-major [M,K], W row-major [N,K]  (torch Linear: x @ W.T + b)
// 128x128 block, BK=8, 256 threads, 8x8 per-thread micro-tile,
// software-pipelined global loads.
// SCATTER=true  -> write into [B,H,S,Hd] layout (QKV projections)
// SCATTER=false -> write row-major [M,N] (output projection)
// ---------------------------------------------------------------------------
template <bool SCATTER>
__global__ __launch_bounds__(256)
void gemm_nt_kernel(const float* __restrict__ A, const float* __restrict__ W,
                    const float* __restrict__ bias, float* __restrict__ C)
{
    const int K = D_MODEL;
    __shared__ float As[8][128];
    __shared__ float Ws[8][128];

    const int tid = threadIdx.x;
    const int tx  = tid & 15;       // 0..15 -> N micro-tile
    const int ty  = tid >> 4;       // 0..15 -> M micro-tile
    const int m0  = blockIdx.y * 128;
    const int n0  = blockIdx.x * 128;

    // cooperative tile loads: one float4 of A and one of W per thread per iter
    const int lrow = tid >> 1;            // 0..127
    const int lcol = (tid & 1) * 4;       // 0 or 4
    const float* aptr = A + (size_t)(m0 + lrow) * K + lcol;
    const float* wptr = W + (size_t)(n0 + lrow) * K + lcol;

    float acc[8][8];
#pragma unroll
    for (int i = 0; i < 8; i++)
#pragma unroll
        for (int j = 0; j < 8; j++) acc[i][j] = 0.f;

    float4 av = *(const float4*)(aptr);
    float4 wv = *(const float4*)(wptr);

    for (int k0 = 0; k0 < K; k0 += 8) {
        __syncthreads();
        As[lcol + 0][lrow] = av.x; As[lcol + 1][lrow] = av.y;
        As[lcol + 2][lrow] = av.z; As[lcol + 3][lrow] = av.w;
        Ws[lcol + 0][lrow] = wv.x; Ws[lcol + 1][lrow] = wv.y;
        Ws[lcol + 2][lrow] = wv.z; Ws[lcol + 3][lrow] = wv.w;
        __syncthreads();

        // prefetch next tile while computing this one
        if (k0 + 8 < K) {
            av = *(const float4*)(aptr + k0 + 8);
            wv = *(const float4*)(wptr + k0 + 8);
        }

#pragma unroll
        for (int k = 0; k < 8; k++) {
            float a[8], w[8];
            *(float4*)(a)     = *(const float4*)&As[k][ty * 8];
            *(float4*)(a + 4) = *(const float4*)&As[k][ty * 8 + 4];
            *(float4*)(w)     = *(const float4*)&Ws[k][tx * 8];
            *(float4*)(w + 4) = *(const float4*)&Ws[k][tx * 8 + 4];
#pragma unroll
            for (int i = 0; i < 8; i++)
#pragma unroll
                for (int j = 0; j < 8; j++)
                    acc[i][j] = fmaf(a[i], w[j], acc[i][j]);
        }
    }

    float bi[8];
#pragma unroll
    for (int j = 0; j < 8; j++) bi[j] = bias[n0 + tx * 8 + j];

#pragma unroll
    for (int i = 0; i < 8; i++) {
        const int m = m0 + ty * 8 + i;
#pragma unroll
        for (int jj = 0; jj < 8; jj += 4) {
            const int n = n0 + tx * 8 + jj;
            float4 v;
            v.x = acc[i][jj + 0] + bi[jj + 0];
            v.y = acc[i][jj + 1] + bi[jj + 1];
            v.z = acc[i][jj + 2] + bi[jj + 2];
            v.w = acc[i][jj + 3] + bi[jj + 3];
            if (SCATTER) {
                // y[m, n] -> Q[b, h, s, hd]; m = b*SEQ + s, n = h*64 + hd
                const int b  = m >> 11;           // / SEQ
                const int s  = m & (SEQ - 1);
                const int h  = n >> 6;            // / HEAD_DIM
                const int hd = n & 63;
                *(float4*)(C + ((size_t)((b * NUM_HEADS + h) * SEQ + s)) * HEAD_DIM + hd) = v;
            } else {
                *(float4*)(C + (size_t)m * D_MODEL + n) = v;
            }
        }
    }
}

// ---------------------------------------------------------------------------
// Flash attention, fp32. One block per (q-tile of 64, b*h). 256 threads.
// Br = Bc = 64, Hd = 64. Thread (ty,tx) owns rows ty*4..+3 and cols tx*4..+3.
// Online softmax; row statistics reduced with shuffles over the 16-lane tx
// group (lane = (ty&1)*16 + tx, xor masks 1,2,4,8 stay inside the group).
// Output written directly in [B,S,D] layout so the O-proj is a plain GEMM.
// ---------------------------------------------------------------------------
__global__ __launch_bounds__(256)
void flash_attn_kernel(const float* __restrict__ Q, const float* __restrict__ K,
                       const float* __restrict__ V, float* __restrict__ AO)
{
    extern __shared__ float sm[];
    float* Qs = sm;                        // [64][68]  (pad 68 vs banks)
    float* Ks = sm + 64 * 68;              // [64][68]
    float* Vs = sm + 2 * 64 * 68;          // [64][64]
    float* Ps = sm + 2 * 64 * 68 + 64 * 64;// [64][64]

    const int tid = threadIdx.x;
    const int tx  = tid & 15;
    const int ty  = tid >> 4;
    const int bh  = blockIdx.y;            // b*NUM_HEADS + h
    const int q0  = blockIdx.x * 64;
    const float scale = 0.125f;            // HEAD_DIM^-0.5

    const float* Qb = Q + (size_t)bh * SEQ * HEAD_DIM;
    const float* Kb = K + (size_t)bh * SEQ * HEAD_DIM;
    const float* Vb = V + (size_t)bh * SEQ * HEAD_DIM;

    // Load Q tile, pre-scaled
#pragma unroll
    for (int it = 0; it < 4; it++) {
        int idx = tid + it * 256;          // 0..1023 float4 slots
        int r   = idx >> 4;
        int c4  = (idx & 15) * 4;
        float4 qv = *(const float4*)(Qb + (size_t)(q0 + r) * HEAD_DIM + c4);
        qv.x *= scale; qv.y *= scale; qv.z *= scale; qv.w *= scale;
        *(float4*)&Qs[r * 68 + c4] = qv;
    }

    float m_r[4], l_r[4], o[4][4];
#pragma unroll
    for (int i = 0; i < 4; i++) {
        m_r[i] = -1e30f; l_r[i] = 0.f;
#pragma unroll
        for (int j = 0; j < 4; j++) o[i][j] = 0.f;
    }

    for (int kv0 = 0; kv0 < SEQ; kv0 += 64) {
        __syncthreads();   // previous iter's PV done before overwriting K/V/P
#pragma unroll
        for (int it = 0; it < 4; it++) {
            int idx = tid + it * 256;
            int r   = idx >> 4;
            int c4  = (idx & 15) * 4;
            *(float4*)&Ks[r * 68 + c4] =
                *(const float4*)(Kb + (size_t)(kv0 + r) * HEAD_DIM + c4);
            *(float4*)&Vs[r * 64 + c4] =
                *(const float4*)(Vb + (size_t)(kv0 + r) * HEAD_DIM + c4);
        }
        __syncthreads();

        // S = Q K^T  (4x4 per thread, K-dim vectorized by 4)
        float s[4][4];
#pragma unroll
        for (int i = 0; i < 4; i++)
#pragma unroll
            for (int j = 0; j < 4; j++) s[i][j] = 0.f;

        for (int k = 0; k < 64; k += 4) {
            float qf[4][4], kf[4][4];
#pragma unroll
            for (int i = 0; i < 4; i++)
                *(float4*)qf[i] = *(const float4*)&Qs[(ty * 4 + i) * 68 + k];
#pragma unroll
            for (int j = 0; j < 4; j++)
                *(float4*)kf[j] = *(const float4*)&Ks[(tx * 4 + j) * 68 + k];
#pragma unroll
            for (int kk = 0; kk < 4; kk++)
#pragma unroll
                for (int i = 0; i < 4; i++)
#pragma unroll
                    for (int j = 0; j < 4; j++)
                        s[i][j] = fmaf(qf[i][kk], kf[j][kk], s[i][j]);
        }

        // Online softmax update + stage P
#pragma unroll
        for (int i = 0; i < 4; i++) {
            float rm = fmaxf(fmaxf(s[i][0], s[i][1]), fmaxf(s[i][2], s[i][3]));
            rm = fmaxf(rm, __shfl_xor_sync(0xffffffffu, rm, 8));
            rm = fmaxf(rm, __shfl_xor_sync(0xffffffffu, rm, 4));
            rm = fmaxf(rm, __shfl_xor_sync(0xffffffffu, rm, 2));
            rm = fmaxf(rm, __shfl_xor_sync(0xffffffffu, rm, 1));
            float mn    = fmaxf(m_r[i], rm);
            float alpha = __expf(m_r[i] - mn);
            m_r[i] = mn;
            float rs = 0.f;
#pragma unroll
            for (int j = 0; j < 4; j++) {
                s[i][j] = __expf(s[i][j] - mn);
                rs += s[i][j];
            }
            rs += __shfl_xor_sync(0xffffffffu, rs, 8);
            rs += __shfl_xor_sync(0xffffffffu, rs, 4);
            rs += __shfl_xor_sync(0xffffffffu, rs, 2);
            rs += __shfl_xor_sync(0xffffffffu, rs, 1);
            l_r[i] = l_r[i] * alpha + rs;
#pragma unroll
            for (int j = 0; j < 4; j++) o[i][j] *= alpha;
            *(float4*)&Ps[(ty * 4 + i) * 64 + tx * 4] =
                make_float4(s[i][0], s[i][1], s[i][2], s[i][3]);
        }
        __syncthreads();

        // O += P V
        for (int c = 0; c < 64; c += 4) {
            float pf[4][4], vf[4][4];
#pragma unroll
            for (int i = 0; i < 4; i++)
                *(float4*)pf[i] = *(const float4*)&Ps[(ty * 4 + i) * 64 + c];
#pragma unroll
            for (int cc = 0; cc < 4; cc++)
                *(float4*)vf[cc] = *(const float4*)&Vs[(c + cc) * 64 + tx * 4];
#pragma unroll
            for (int cc = 0; cc < 4; cc++)
#pragma unroll
                for (int i = 0; i < 4; i++)
#pragma unroll
                    for (int j = 0; j < 4; j++)
                        o[i][j] = fmaf(pf[i][cc], vf[cc][j], o[i][j]);
        }
    }

    // Epilogue: normalize, write [B,S,D] layout
    const int b = bh >> 4;        // / NUM_HEADS
    const int h = bh & 15;
#pragma unroll
    for (int i = 0; i < 4; i++) {
        const float inv  = 1.0f / l_r[i];
        const int   srow = q0 + ty * 4 + i;
        float4 ov = make_float4(o[i][0] * inv, o[i][1] * inv,
                                o[i][2] * inv, o[i][3] * inv);
        *(float4*)(AO + ((size_t)(b * SEQ + srow)) * D_MODEL + h * HEAD_DIM + tx * 4) = ov;
    }
}

// ---------------------------------------------------------------------------
extern "C" void kernel_launch(void* const* d_in, const int* in_sizes, int n_in,
                              void* d_out, int out_size)
{
    const float* x  = (const float*)d_in[0];
    const float* wq = (const float*)d_in[1];
    const float* bq = (const float*)d_in[2];
    const float* wk = (const float*)d_in[3];
    const float* bk = (const float*)d_in[4];
    const float* wv = (const float*)d_in[5];
    const float* bv = (const float*)d_in[6];
    const float* wo = (const float*)d_in[7];
    const float* bo = (const float*)d_in[8];

    float *Qp, *Kp, *Vp, *AOp;
    cudaGetSymbolAddress((void**)&Qp,  g_Q);
    cudaGetSymbolAddress((void**)&Kp,  g_K);
    cudaGetSymbolAddress((void**)&Vp,  g_V);
    cudaGetSymbolAddress((void**)&AOp, g_AO);

    const dim3 pg(D_MODEL / 128, MTOT / 128);   // (8, 64)

    gemm_nt_kernel<true><<<pg, 256>>>(x, wq, bq, Qp);
    gemm_nt_kernel<true><<<pg, 256>>>(x, wk, bk, Kp);
    gemm_nt_kernel<true><<<pg, 256>>>(x, wv, bv, Vp);

    const int smem = (2 * 64 * 68 + 2 * 64 * 64) * (int)sizeof(float); // 67584 B
    cudaFuncSetAttribute(flash_attn_kernel,
                         cudaFuncAttributeMaxDynamicSharedMemorySize, smem);
    flash_attn_kernel<<<dim3(SEQ / 64, BATCH * NUM_HEADS), 256, smem>>>(Qp, Kp, Vp, AOp);

    gemm_nt_kernel<false><<<pg, 256>>>(AOp, wo, bo, (float*)d_out);
}

// round 3
// speedup vs baseline: 1.0004x; 1.0004x over previous
#include <cuda_runtime.h>

#define D_MODEL   1024
#define NUM_HEADS 16
#define HEAD_DIM  64
#define BATCH     4
#define SEQ       2048
#define MTOT      (BATCH * SEQ)

// Scratch (allocation-free: __device__ globals). 4 x 32 MB.
__device__ float g_Q [MTOT * D_MODEL];
__device__ float g_K [MTOT * D_MODEL];
__device__ float g_V [MTOT * D_MODEL];
__device__ float g_AO[MTOT * D_MODEL];

// ---------------------------------------------------------------------------
// GEMM (NT): C[M,N] = A[M,K] @ W[N,K]^T + bias[N]
// A row-major [M,K], W row-major [N,K]  (torch Linear: x @ W.T + b)
// 128x128 block, BK=8, 256 threads, 8x8 per-thread micro-tile,
// software-pipelined global loads.
// SCATTER=true  -> write into [B,H,S,Hd] layout (QKV projections)
// SCATTER=false -> write row-major [M,N] (output projection)
// ---------------------------------------------------------------------------
template <bool SCATTER>
__global__ __launch_bounds__(256)
void gemm_nt_kernel(const float* __restrict__ A, const float* __restrict__ W,
                    const float* __restrict__ bias, float* __restrict__ C)
{
    const int K = D_MODEL;
    __shared__ float As[8][128];
    __shared__ float Ws[8][128];

    const int tid = threadIdx.x;
    const int tx  = tid & 15;       // 0..15 -> N micro-tile
    const int ty  = tid >> 4;       // 0..15 -> M micro-tile
    const int m0  = blockIdx.y * 128;
    const int n0  = blockIdx.x * 128;

    // cooperative tile loads: one float4 of A and one of W per thread per iter
    const int lrow = tid >> 1;            // 0..127
    const int lcol = (tid & 1) * 4;       // 0 or 4
    const float* aptr = A + (size_t)(m0 + lrow) * K + lcol;
    const float* wptr = W + (size_t)(n0 + lrow) * K + lcol;

    float acc[8][8];
#pragma unroll
    for (int i = 0; i < 8; i++)
#pragma unroll
        for (int j = 0; j < 8; j++) acc[i][j] = 0.f;

    float4 av = *(const float4*)(aptr);
    float4 wv = *(const float4*)(wptr);

    for (int k0 = 0; k0 < K; k0 += 8) {
        __syncthreads();
        As[lcol + 0][lrow] = av.x; As[lcol + 1][lrow] = av.y;
        As[lcol + 2][lrow] = av.z; As[lcol + 3][lrow] = av.w;
        Ws[lcol + 0][lrow] = wv.x; Ws[lcol + 1][lrow] = wv.y;
        Ws[lcol + 2][lrow] = wv.z; Ws[lcol + 3][lrow] = wv.w;
        __syncthreads();

        // prefetch next tile while computing this one
        if (k0 + 8 < K) {
            av = *(const float4*)(aptr + k0 + 8);
            wv = *(const float4*)(wptr + k0 + 8);
        }

#pragma unroll
        for (int k = 0; k < 8; k++) {
            float a[8], w[8];
            *(float4*)(a)     = *(const float4*)&As[k][ty * 8];
            *(float4*)(a + 4) = *(const float4*)&As[k][ty * 8 + 4];
            *(float4*)(w)     = *(const float4*)&Ws[k][tx * 8];
            *(float4*)(w + 4) = *(const float4*)&Ws[k][tx * 8 + 4];
#pragma unroll
            for (int i = 0; i < 8; i++)
#pragma unroll
                for (int j = 0; j < 8; j++)
                    acc[i][j] = fmaf(a[i], w[j], acc[i][j]);
        }
    }

    float bi[8];
#pragma unroll
    for (int j = 0; j < 8; j++) bi[j] = bias[n0 + tx * 8 + j];

#pragma unroll
    for (int i = 0; i < 8; i++) {
        const int m = m0 + ty * 8 + i;
#pragma unroll
        for (int jj = 0; jj < 8; jj += 4) {
            const int n = n0 + tx * 8 + jj;
            float4 v;
            v.x = acc[i][jj + 0] + bi[jj + 0];
            v.y = acc[i][jj + 1] + bi[jj + 1];
            v.z = acc[i][jj + 2] + bi[jj + 2];
            v.w = acc[i][jj + 3] + bi[jj + 3];
            if (SCATTER) {
                // y[m, n] -> Q[b, h, s, hd]; m = b*SEQ + s, n = h*64 + hd
                const int b  = m >> 11;           // / SEQ
                const int s  = m & (SEQ - 1);
                const int h  = n >> 6;            // / HEAD_DIM
                const int hd = n & 63;
                *(float4*)(C + ((size_t)((b * NUM_HEADS + h) * SEQ + s)) * HEAD_DIM + hd) = v;
            } else {
                *(float4*)(C + (size_t)m * D_MODEL + n) = v;
            }
        }
    }
}

// ---------------------------------------------------------------------------
// Flash attention, fp32. One block per (q-tile of 64, b*h). 256 threads.
// Br = Bc = 64, Hd = 64. Thread (ty,tx) owns rows ty*4..+3 and cols tx*4..+3.
// Online softmax; row statistics reduced with shuffles over the 16-lane tx
// group (lane = (ty&1)*16 + tx, xor masks 1,2,4,8 stay inside the group).
// Output written directly in [B,S,D] layout so the O-proj is a plain GEMM.
// ---------------------------------------------------------------------------
__global__ __launch_bounds__(256)
void flash_attn_kernel(const float* __restrict__ Q, const float* __restrict__ K,
                       const float* __restrict__ V, float* __restrict__ AO)
{
    extern __shared__ float sm[];
    float* Qs = sm;                        // [64][68]  (pad 68 vs banks)
    float* Ks = sm + 64 * 68;              // [64][68]
    float* Vs = sm + 2 * 64 * 68;          // [64][64]
    float* Ps = sm + 2 * 64 * 68 + 64 * 64;// [64][64]

    const int tid = threadIdx.x;
    const int tx  = tid & 15;
    const int ty  = tid >> 4;
    const int bh  = blockIdx.y;            // b*NUM_HEADS + h
    const int q0  = blockIdx.x * 64;
    const float scale = 0.125f;            // HEAD_DIM^-0.5

    const float* Qb = Q + (size_t)bh * SEQ * HEAD_DIM;
    const float* Kb = K + (size_t)bh * SEQ * HEAD_DIM;
    const float* Vb = V + (size_t)bh * SEQ * HEAD_DIM;

    // Load Q tile, pre-scaled
#pragma unroll
    for (int it = 0; it < 4; it++) {
        int idx = tid + it * 256;          // 0..1023 float4 slots
        int r   = idx >> 4;
        int c4  = (idx & 15) * 4;
        float4 qv = *(const float4*)(Qb + (size_t)(q0 + r) * HEAD_DIM + c4);
        qv.x *= scale; qv.y *= scale; qv.z *= scale; qv.w *= scale;
        *(float4*)&Qs[r * 68 + c4] = qv;
    }

    float m_r[4], l_r[4], o[4][4];
#pragma unroll
    for (int i = 0; i < 4; i++) {
        m_r[i] = -1e30f; l_r[i] = 0.f;
#pragma unroll
        for (int j = 0; j < 4; j++) o[i][j] = 0.f;
    }

    for (int kv0 = 0; kv0 < SEQ; kv0 += 64) {
        __syncthreads();   // previous iter's PV done before overwriting K/V/P
#pragma unroll
        for (int it = 0; it < 4; it++) {
            int idx = tid + it * 256;
            int r   = idx >> 4;
            int c4  = (idx & 15) * 4;
            *(float4*)&Ks[r * 68 + c4] =
                *(const float4*)(Kb + (size_t)(kv0 + r) * HEAD_DIM + c4);
            *(float4*)&Vs[r * 64 + c4] =
                *(const float4*)(Vb + (size_t)(kv0 + r) * HEAD_DIM + c4);
        }
        __syncthreads();

        // S = Q K^T  (4x4 per thread, K-dim vectorized by 4)
        float s[4][4];
#pragma unroll
        for (int i = 0; i < 4; i++)
#pragma unroll
            for (int j = 0; j < 4; j++) s[i][j] = 0.f;

        for (int k = 0; k < 64; k += 4) {
            float qf[4][4], kf[4][4];
#pragma unroll
            for (int i = 0; i < 4; i++)
                *(float4*)qf[i] = *(const float4*)&Qs[(ty * 4 + i) * 68 + k];
#pragma unroll
            for (int j = 0; j < 4; j++)
                *(float4*)kf[j] = *(const float4*)&Ks[(tx * 4 + j) * 68 + k];
#pragma unroll
            for (int kk = 0; kk < 4; kk++)
#pragma unroll
                for (int i = 0; i < 4; i++)
#pragma unroll
                    for (int j = 0; j < 4; j++)
                        s[i][j] = fmaf(qf[i][kk], kf[j][kk], s[i][j]);
        }

        // Online softmax update + stage P
#pragma unroll
        for (int i = 0; i < 4; i++) {
            float rm = fmaxf(fmaxf(s[i][0], s[i][1]), fmaxf(s[i][2], s[i][3]));
            rm = fmaxf(rm, __shfl_xor_sync(0xffffffffu, rm, 8));
            rm = fmaxf(rm, __shfl_xor_sync(0xffffffffu, rm, 4));
            rm = fmaxf(rm, __shfl_xor_sync(0xffffffffu, rm, 2));
            rm = fmaxf(rm, __shfl_xor_sync(0xffffffffu, rm, 1));
            float mn    = fmaxf(m_r[i], rm);
            float alpha = __expf(m_r[i] - mn);
            m_r[i] = mn;
            float rs = 0.f;
#pragma unroll
            for (int j = 0; j < 4; j++) {
                s[i][j] = __expf(s[i][j] - mn);
                rs += s[i][j];
            }
            rs += __shfl_xor_sync(0xffffffffu, rs, 8);
            rs += __shfl_xor_sync(0xffffffffu, rs, 4);
            rs += __shfl_xor_sync(0xffffffffu, rs, 2);
            rs += __shfl_xor_sync(0xffffffffu, rs, 1);
            l_r[i] = l_r[i] * alpha + rs;
#pragma unroll
            for (int j = 0; j < 4; j++) o[i][j] *= alpha;
            *(float4*)&Ps[(ty * 4 + i) * 64 + tx * 4] =
                make_float4(s[i][0], s[i][1], s[i][2], s[i][3]);
        }
        __syncthreads();

        // O += P V
        for (int c = 0; c < 64; c += 4) {
            float pf[4][4], vf[4][4];
#pragma unroll
            for (int i = 0; i < 4; i++)
                *(float4*)pf[i] = *(const float4*)&Ps[(ty * 4 + i) * 64 + c];
#pragma unroll
            for (int cc = 0; cc < 4; cc++)
                *(float4*)vf[cc] = *(const float4*)&Vs[(c + cc) * 64 + tx * 4];
#pragma unroll
            for (int cc = 0; cc < 4; cc++)
#pragma unroll
                for (int i = 0; i < 4; i++)
#pragma unroll
                    for (int j = 0; j < 4; j++)
                        o[i][j] = fmaf(pf[i][cc], vf[cc][j], o[i][j]);
        }
    }

    // Epilogue: normalize, write [B,S,D] layout
    const int b = bh >> 4;        // / NUM_HEADS
    const int h = bh & 15;
#pragma unroll
    for (int i = 0; i < 4; i++) {
        const float inv  = 1.0f / l_r[i];
        const int   srow = q0 + ty * 4 + i;
        float4 ov = make_float4(o[i][0] * inv, o[i][1] * inv,
                                o[i][2] * inv, o[i][3] * inv);
        *(float4*)(AO + ((size_t)(b * SEQ + srow)) * D_MODEL + h * HEAD_DIM + tx * 4) = ov;
    }
}

// ---------------------------------------------------------------------------
extern "C" void kernel_launch(void* const* d_in, const int* in_sizes, int n_in,
                              void* d_out, int out_size)
{
    const float* x  = (const float*)d_in[0];
    const float* wq = (const float*)d_in[1];
    const float* bq = (const float*)d_in[2];
    const float* wk = (const float*)d_in[3];
    const float* bk = (const float*)d_in[4];
    const float* wv = (const float*)d_in[5];
    const float* bv = (const float*)d_in[6];
    const float* wo = (const float*)d_in[7];
    const float* bo = (const float*)d_in[8];

    float *Qp, *Kp, *Vp, *AOp;
    cudaGetSymbolAddress((void**)&Qp,  g_Q);
    cudaGetSymbolAddress((void**)&Kp,  g_K);
    cudaGetSymbolAddress((void**)&Vp,  g_V);
    cudaGetSymbolAddress((void**)&AOp, g_AO);

    const dim3 pg(D_MODEL / 128, MTOT / 128);   // (8, 64)

    gemm_nt_kernel<true><<<pg, 256>>>(x, wq, bq, Qp);
    gemm_nt_kernel<true><<<pg, 256>>>(x, wk, bk, Kp);
    gemm_nt_kernel<true><<<pg, 256>>>(x, wv, bv, Vp);

    const int smem = (2 * 64 * 68 + 2 * 64 * 64) * (int)sizeof(float); // 67584 B
    cudaFuncSetAttribute(flash_attn_kernel,
                         cudaFuncAttributeMaxDynamicSharedMemorySize, smem);
    flash_attn_kernel<<<dim3(SEQ / 64, BATCH * NUM_HEADS), 256, smem>>>(Qp, Kp, Vp, AOp);

    gemm_nt_kernel<false><<<pg, 256>>>(AOp, wo, bo, (float*)d_out);
}

// round 4
// speedup vs baseline: 1.3796x; 1.3790x over previous
#include <cuda_runtime.h>

#define D_MODEL   1024
#define NUM_HEADS 16
#define HEAD_DIM  64
#define BATCH     4
#define SEQ       2048
#define MTOT      (BATCH * SEQ)

// Scratch (allocation-free: __device__ globals). 4 x 32 MB.
__device__ float g_Q [MTOT * D_MODEL];
__device__ float g_K [MTOT * D_MODEL];
__device__ float g_V [MTOT * D_MODEL];
__device__ float g_AO[MTOT * D_MODEL];

// ---------------------------------------------------------------------------
// GEMM (NT): C[M,N] = A[M,K] @ W[N,K]^T + bias[N]    (unchanged from R2;
// measured at ~38 TF/s fp32 = FFMA roofline)
// ---------------------------------------------------------------------------
template <bool SCATTER>
__global__ __launch_bounds__(256)
void gemm_nt_kernel(const float* __restrict__ A, const float* __restrict__ W,
                    const float* __restrict__ bias, float* __restrict__ C)
{
    const int K = D_MODEL;
    __shared__ float As[8][128];
    __shared__ float Ws[8][128];

    const int tid = threadIdx.x;
    const int tx  = tid & 15;
    const int ty  = tid >> 4;
    const int m0  = blockIdx.y * 128;
    const int n0  = blockIdx.x * 128;

    const int lrow = tid >> 1;
    const int lcol = (tid & 1) * 4;
    const float* aptr = A + (size_t)(m0 + lrow) * K + lcol;
    const float* wptr = W + (size_t)(n0 + lrow) * K + lcol;

    float acc[8][8];
#pragma unroll
    for (int i = 0; i < 8; i++)
#pragma unroll
        for (int j = 0; j < 8; j++) acc[i][j] = 0.f;

    float4 av = *(const float4*)(aptr);
    float4 wv = *(const float4*)(wptr);

    for (int k0 = 0; k0 < K; k0 += 8) {
        __syncthreads();
        As[lcol + 0][lrow] = av.x; As[lcol + 1][lrow] = av.y;
        As[lcol + 2][lrow] = av.z; As[lcol + 3][lrow] = av.w;
        Ws[lcol + 0][lrow] = wv.x; Ws[lcol + 1][lrow] = wv.y;
        Ws[lcol + 2][lrow] = wv.z; Ws[lcol + 3][lrow] = wv.w;
        __syncthreads();

        if (k0 + 8 < K) {
            av = *(const float4*)(aptr + k0 + 8);
            wv = *(const float4*)(wptr + k0 + 8);
        }

#pragma unroll
        for (int k = 0; k < 8; k++) {
            float a[8], w[8];
            *(float4*)(a)     = *(const float4*)&As[k][ty * 8];
            *(float4*)(a + 4) = *(const float4*)&As[k][ty * 8 + 4];
            *(float4*)(w)     = *(const float4*)&Ws[k][tx * 8];
            *(float4*)(w + 4) = *(const float4*)&Ws[k][tx * 8 + 4];
#pragma unroll
            for (int i = 0; i < 8; i++)
#pragma unroll
                for (int j = 0; j < 8; j++)
                    acc[i][j] = fmaf(a[i], w[j], acc[i][j]);
        }
    }

    float bi[8];
#pragma unroll
    for (int j = 0; j < 8; j++) bi[j] = bias[n0 + tx * 8 + j];

#pragma unroll
    for (int i = 0; i < 8; i++) {
        const int m = m0 + ty * 8 + i;
#pragma unroll
        for (int jj = 0; jj < 8; jj += 4) {
            const int n = n0 + tx * 8 + jj;
            float4 v;
            v.x = acc[i][jj + 0] + bi[jj + 0];
            v.y = acc[i][jj + 1] + bi[jj + 1];
            v.z = acc[i][jj + 2] + bi[jj + 2];
            v.w = acc[i][jj + 3] + bi[jj + 3];
            if (SCATTER) {
                const int b  = m >> 11;
                const int s  = m & (SEQ - 1);
                const int h  = n >> 6;
                const int hd = n & 63;
                *(float4*)(C + ((size_t)((b * NUM_HEADS + h) * SEQ + s)) * HEAD_DIM + hd) = v;
            } else {
                *(float4*)(C + (size_t)m * D_MODEL + n) = v;
            }
        }
    }
}

// ---------------------------------------------------------------------------
// Flash attention v2, fp32. Br = Bc = 128, Hd = 64, 256 threads.
// QK^T: 8x8 micro-tile (0.5 B smem / FLOP), K held TRANSPOSED in smem
// (Kt[k][n], stride 132) so K-fragment loads are contiguous float4 and Q
// fragment loads are pure broadcasts -> conflict-free.
// PV: 8 rows x 4 cols per thread; P staged via smem (broadcast reads).
// Online softmax over the 16-lane tx group (xor 1,2,4,8 stay in-group).
// ---------------------------------------------------------------------------
#define QS_STRIDE 68
#define KT_STRIDE 132
#define FA_SMEM ((128*QS_STRIDE + 64*KT_STRIDE + 128*64 + 128*128) * 4)

__global__ __launch_bounds__(256, 1)
void flash_attn_kernel(const float* __restrict__ Q, const float* __restrict__ K,
                       const float* __restrict__ V, float* __restrict__ AO)
{
    extern __shared__ float sm[];
    float* Qs = sm;                                   // [128][68]
    float* Kt = Qs + 128 * QS_STRIDE;                 // [64][132] (transposed)
    float* Vs = Kt + 64 * KT_STRIDE;                  // [128][64]
    float* Ps = Vs + 128 * 64;                        // [128][128]

    const int tid = threadIdx.x;
    const int tx  = tid & 15;
    const int ty  = tid >> 4;
    const int bh  = blockIdx.y;
    const int q0  = blockIdx.x * 128;
    const float scale = 0.125f;                       // HEAD_DIM^-0.5

    const float* Qb = Q + (size_t)bh * SEQ * HEAD_DIM;
    const float* Kb = K + (size_t)bh * SEQ * HEAD_DIM;
    const float* Vb = V + (size_t)bh * SEQ * HEAD_DIM;

    // Load Q tile (128x64), pre-scaled. 2048 float4 slots / 256 threads.
#pragma unroll
    for (int it = 0; it < 8; it++) {
        int idx = tid + it * 256;
        int r   = idx >> 4;
        int c4  = (idx & 15) * 4;
        float4 qv = *(const float4*)(Qb + (size_t)(q0 + r) * HEAD_DIM + c4);
        qv.x *= scale; qv.y *= scale; qv.z *= scale; qv.w *= scale;
        *(float4*)&Qs[r * QS_STRIDE + c4] = qv;
    }

    float m_r[8], l_r[8], o[8][4];
#pragma unroll
    for (int i = 0; i < 8; i++) {
        m_r[i] = -1e30f; l_r[i] = 0.f;
#pragma unroll
        for (int j = 0; j < 4; j++) o[i][j] = 0.f;
    }

    for (int kv0 = 0; kv0 < SEQ; kv0 += 128) {
        __syncthreads();   // previous iter's PV reads done before overwrite
        // K: load + transpose into Kt[k][n]; V: straight copy.
#pragma unroll
        for (int it = 0; it < 8; it++) {
            int idx = tid + it * 256;
            int r   = idx >> 4;           // 0..127 (kv row within tile)
            int c4  = (idx & 15) * 4;     // 0..60  (head-dim)
            float4 kv4 = *(const float4*)(Kb + (size_t)(kv0 + r) * HEAD_DIM + c4);
            Kt[(c4 + 0) * KT_STRIDE + r] = kv4.x;
            Kt[(c4 + 1) * KT_STRIDE + r] = kv4.y;
            Kt[(c4 + 2) * KT_STRIDE + r] = kv4.z;
            Kt[(c4 + 3) * KT_STRIDE + r] = kv4.w;
            *(float4*)&Vs[r * 64 + c4] =
                *(const float4*)(Vb + (size_t)(kv0 + r) * HEAD_DIM + c4);
        }
        __syncthreads();

        // ---- S = Q K^T : 8x8 per thread over a 128x128 tile ----
        float s[8][8];
#pragma unroll
        for (int i = 0; i < 8; i++)
#pragma unroll
            for (int j = 0; j < 8; j++) s[i][j] = 0.f;

        for (int k = 0; k < 64; k += 4) {
            float qf[8][4];
#pragma unroll
            for (int i = 0; i < 8; i++)       // broadcast loads
                *(float4*)qf[i] = *(const float4*)&Qs[(ty * 8 + i) * QS_STRIDE + k];
#pragma unroll
            for (int kk = 0; kk < 4; kk++) {
                float kf[8];
                *(float4*)(kf)     = *(const float4*)&Kt[(k + kk) * KT_STRIDE + tx * 8];
                *(float4*)(kf + 4) = *(const float4*)&Kt[(k + kk) * KT_STRIDE + tx * 8 + 4];
#pragma unroll
                for (int i = 0; i < 8; i++)
#pragma unroll
                    for (int j = 0; j < 8; j++)
                        s[i][j] = fmaf(qf[i][kk], kf[j], s[i][j]);
            }
        }

        // ---- online softmax + stage P ----
#pragma unroll
        for (int i = 0; i < 8; i++) {
            float rm = s[i][0];
#pragma unroll
            for (int j = 1; j < 8; j++) rm = fmaxf(rm, s[i][j]);
            rm = fmaxf(rm, __shfl_xor_sync(0xffffffffu, rm, 8));
            rm = fmaxf(rm, __shfl_xor_sync(0xffffffffu, rm, 4));
            rm = fmaxf(rm, __shfl_xor_sync(0xffffffffu, rm, 2));
            rm = fmaxf(rm, __shfl_xor_sync(0xffffffffu, rm, 1));
            float mn    = fmaxf(m_r[i], rm);
            float alpha = __expf(m_r[i] - mn);
            m_r[i] = mn;
            float rs = 0.f;
#pragma unroll
            for (int j = 0; j < 8; j++) {
                s[i][j] = __expf(s[i][j] - mn);
                rs += s[i][j];
            }
            rs += __shfl_xor_sync(0xffffffffu, rs, 8);
            rs += __shfl_xor_sync(0xffffffffu, rs, 4);
            rs += __shfl_xor_sync(0xffffffffu, rs, 2);
            rs += __shfl_xor_sync(0xffffffffu, rs, 1);
            l_r[i] = l_r[i] * alpha + rs;
#pragma unroll
            for (int j = 0; j < 4; j++) o[i][j] *= alpha;
            *(float4*)&Ps[(ty * 8 + i) * 128 + tx * 8] =
                make_float4(s[i][0], s[i][1], s[i][2], s[i][3]);
            *(float4*)&Ps[(ty * 8 + i) * 128 + tx * 8 + 4] =
                make_float4(s[i][4], s[i][5], s[i][6], s[i][7]);
        }
        __syncthreads();

        // ---- O += P V : thread = 8 rows (ty*8+i) x 4 cols (tx*4) ----
        for (int c = 0; c < 128; c += 4) {
            float pf[8][4];
#pragma unroll
            for (int i = 0; i < 8; i++)       // broadcast loads
                *(float4*)pf[i] = *(const float4*)&Ps[(ty * 8 + i) * 128 + c];
#pragma unroll
            for (int cc = 0; cc < 4; cc++) {
                float4 vv = *(const float4*)&Vs[(c + cc) * 64 + tx * 4];
#pragma unroll
                for (int i = 0; i < 8; i++) {
                    o[i][0] = fmaf(pf[i][cc], vv.x, o[i][0]);
                    o[i][1] = fmaf(pf[i][cc], vv.y, o[i][1]);
                    o[i][2] = fmaf(pf[i][cc], vv.z, o[i][2]);
                    o[i][3] = fmaf(pf[i][cc], vv.w, o[i][3]);
                }
            }
        }
    }

    // Epilogue: normalize, write [B,S,D] layout
    const int b = bh >> 4;
    const int h = bh & 15;
#pragma unroll
    for (int i = 0; i < 8; i++) {
        const float inv  = 1.0f / l_r[i];
        const int   srow = q0 + ty * 8 + i;
        float4 ov = make_float4(o[i][0] * inv, o[i][1] * inv,
                                o[i][2] * inv, o[i][3] * inv);
        *(float4*)(AO + ((size_t)(b * SEQ + srow)) * D_MODEL + h * HEAD_DIM + tx * 4) = ov;
    }
}

// ---------------------------------------------------------------------------
extern "C" void kernel_launch(void* const* d_in, const int* in_sizes, int n_in,
                              void* d_out, int out_size)
{
    const float* x  = (const float*)d_in[0];
    const float* wq = (const float*)d_in[1];
    const float* bq = (const float*)d_in[2];
    const float* wk = (const float*)d_in[3];
    const float* bk = (const float*)d_in[4];
    const float* wv = (const float*)d_in[5];
    const float* bv = (const float*)d_in[6];
    const float* wo = (const float*)d_in[7];
    const float* bo = (const float*)d_in[8];

    float *Qp, *Kp, *Vp, *AOp;
    cudaGetSymbolAddress((void**)&Qp,  g_Q);
    cudaGetSymbolAddress((void**)&Kp,  g_K);
    cudaGetSymbolAddress((void**)&Vp,  g_V);
    cudaGetSymbolAddress((void**)&AOp, g_AO);

    const dim3 pg(D_MODEL / 128, MTOT / 128);   // (8, 64)

    gemm_nt_kernel<true><<<pg, 256>>>(x, wq, bq, Qp);
    gemm_nt_kernel<true><<<pg, 256>>>(x, wk, bk, Kp);
    gemm_nt_kernel<true><<<pg, 256>>>(x, wv, bv, Vp);

    cudaFuncSetAttribute(flash_attn_kernel,
                         cudaFuncAttributeMaxDynamicSharedMemorySize, FA_SMEM);
    flash_attn_kernel<<<dim3(SEQ / 128, BATCH * NUM_HEADS), 256, FA_SMEM>>>(Qp, Kp, Vp, AOp);

    gemm_nt_kernel<false><<<pg, 256>>>(AOp, wo, bo, (float*)d_out);
}